// round 5
// baseline (speedup 1.0000x reference)
#include <cuda_runtime.h>
#include <cstdint>
#include <cstddef>

#define NS 512
#define NB 1024
#define NT 64

__device__ float g_partial[NB];
__device__ unsigned int g_ctr = 0;

typedef unsigned long long u64;

__device__ __forceinline__ u64 pack2(float lo, float hi) {
    u64 r; asm("mov.b64 %0, {%1, %2};" : "=l"(r) : "f"(lo), "f"(hi)); return r;
}
__device__ __forceinline__ void unpack2(u64 v, float& lo, float& hi) {
    asm("mov.b64 {%0, %1}, %2;" : "=f"(lo), "=f"(hi) : "l"(v));
}
__device__ __forceinline__ void fma2(u64& acc, u64 a, u64 b) {
    asm("fma.rn.f32x2 %0, %1, %2, %0;" : "+l"(acc) : "l"(a), "l"(b));
}
__device__ __forceinline__ u64 add2(u64 a, u64 b) {
    u64 r; asm("add.rn.f32x2 %0, %1, %2;" : "=l"(r) : "l"(a), "l"(b)); return r;
}
__device__ __forceinline__ float frcp(float x) {
    float r; asm("rcp.approx.f32 %0, %1;" : "=f"(r) : "f"(x)); return r;
}

__global__ void __launch_bounds__(64, 8)
crf_kernel(const float* __restrict__ em,
           const float* __restrict__ trans,
           const float* __restrict__ start_t,
           const float* __restrict__ end_t,
           const int* __restrict__ tags,
           const int* __restrict__ mask,
           float* __restrict__ out) {
    __shared__ __align__(16) float ybuf[2][NT];
    __shared__ float rbuf[2];
    __shared__ float wsum[2];   // cross-warp scalar exchange
    __shared__ int   wmsk[2];
    __shared__ int   is_last;

    const int tid  = threadIdx.x;   // 0..63
    const int wid  = tid >> 5;
    const int lane = tid & 31;
    const int b    = blockIdx.x;
    const int j    = tid;           // my tag column
    const size_t SSTR = (size_t)NB * NT;

    // ---------------- numerator: gold-path score over 64 threads ----------------
    float sc = 0.f;
    int msum = 0;
#pragma unroll
    for (int k = 0; k < 8; k++) {
        int s = 1 + tid + (k << 6);
        if (s < NS) {
            int tp = tags[(s - 1) * NB + b];
            int tc = tags[s * NB + b];
            int mv = mask[s * NB + b];
            float term = trans[tp * NT + tc] + em[((size_t)s * NB + b) * NT + tc];
            sc += term * (float)mv;
            msum += mv;
        }
    }
#pragma unroll
    for (int off = 16; off; off >>= 1) {
        sc   += __shfl_xor_sync(0xffffffffu, sc, off);
        msum += __shfl_xor_sync(0xffffffffu, msum, off);
    }
    if (lane == 0) { wsum[wid] = sc; wmsk[wid] = msum; }

    // ---------------- E column j as packed row-pairs (32 u64 regs) ----------------
    u64 Epair[32];
#pragma unroll
    for (int i = 0; i < 32; i++) {
        float e0 = __expf(trans[(2 * i)     * NT + j]);
        float e1 = __expf(trans[(2 * i + 1) * NT + j]);
        Epair[i] = pack2(e0, e1);
    }

    // ---------------- init recursion state ----------------
    const float* emj = em + (size_t)b * NT + j;      // em[s,b,j] at emj + s*SSTR
    float yreg = __expf(start_t[j] + emj[0]);
    ybuf[1][j] = yreg;                               // step 1 reads parity 1
    if (tid == 0) rbuf[1] = 1.0f;
    float Mtot = 0.f, lpend = 0.f;                   // meaningful on w0 lane0

    // em prefetch ring (4 deep) + exp one step ahead; mask ring (2 deep)
    float pf0 = emj[1 * SSTR];
    float pf1 = emj[2 * SSTR];
    float pf2 = emj[3 * SSTR];
    float pf3 = emj[4 * SSTR];
    float eemCur = __expf(pf0);
    int mkA = mask[1 * NB + b];
    int mkB = mask[2 * NB + b];

    __syncthreads();

    // numerator finalize on w0 lane0 (after sync so wsum/wmsk visible)
    if (tid == 0) {
        sc = wsum[0] + wsum[1];
        int t0 = tags[b];
        sc += start_t[t0] + em[(size_t)b * NT + t0];
        int seq_end = mask[b] + (wmsk[0] + wmsk[1]) - 1;
        int lt = tags[(size_t)seq_end * NB + b];
        sc += end_t[lt];
    }

#define CRF_STEP(S, PF_USE, PF_WR, MK_SLOT)                                         \
    do {                                                                            \
        if ((S) < NS) {                                                             \
            const int cur = (S) & 1, nxt = cur ^ 1;                                 \
            const int mk = MK_SLOT;                                                 \
            float rcur = rbuf[cur];                                                 \
            const float4* q4 = reinterpret_cast<const float4*>(ybuf[cur]);          \
            u64 A0 = 0, A1 = 0, A2 = 0, A3 = 0;                                     \
            _Pragma("unroll")                                                       \
            for (int k2 = 0; k2 < 16; k2 += 4) {                                    \
                float4 qa = q4[k2], qb = q4[k2 + 1];                                \
                float4 qc = q4[k2 + 2], qd = q4[k2 + 3];                            \
                fma2(A0, pack2(qa.x, qa.y), Epair[2 * k2]);                         \
                fma2(A1, pack2(qa.z, qa.w), Epair[2 * k2 + 1]);                     \
                fma2(A2, pack2(qb.x, qb.y), Epair[2 * k2 + 2]);                     \
                fma2(A3, pack2(qb.z, qb.w), Epair[2 * k2 + 3]);                     \
                fma2(A0, pack2(qc.x, qc.y), Epair[2 * k2 + 4]);                     \
                fma2(A1, pack2(qc.z, qc.w), Epair[2 * k2 + 5]);                     \
                fma2(A2, pack2(qd.x, qd.y), Epair[2 * k2 + 6]);                     \
                fma2(A3, pack2(qd.z, qd.w), Epair[2 * k2 + 7]);                     \
            }                                                                       \
            u64 acc = add2(add2(A0, A1), add2(A2, A3));                             \
            float alo, ahi; unpack2(acc, alo, ahi);                                 \
            float u = (alo + ahi) * rcur;                                           \
            float ycand = u * eemCur;                                               \
            if (mk) yreg = ycand;                                                   \
            ybuf[nxt][j] = yreg;                                                    \
            if (wid == 0) {                                                         \
                float a0u = __shfl_sync(0xffffffffu, u, 0);                         \
                if (lane == 0) {                                                    \
                    rbuf[nxt] = mk ? frcp(a0u) : rcur;                              \
                    Mtot += mk ? lpend : 0.f;                                       \
                    lpend = mk ? __logf(a0u) : lpend;                               \
                }                                                                   \
            }                                                                       \
            __syncthreads();                                                        \
            eemCur = __expf(PF_USE);                                                \
            if ((S) + 4 < NS)                                                       \
                PF_WR = emj[(size_t)((S) + 4) * SSTR];                              \
            if ((S) + 2 < NS)                                                       \
                MK_SLOT = mask[((S) + 2) * NB + b];                                 \
        }                                                                           \
    } while (0)

    for (int k = 0; k < 128; k++) {
        int sb = 1 + (k << 2);
        CRF_STEP(sb,     pf1, pf0, mkA);
        CRF_STEP(sb + 1, pf2, pf1, mkB);
        CRF_STEP(sb + 2, pf3, pf2, mkA);
        CRF_STEP(sb + 3, pf0, pf3, mkB);
    }
#undef CRF_STEP

    // ---------------- final: normalizer = Mtot + log( sum_j y_j * exp(end_j) ) ----------
    {
        float v = yreg * __expf(end_t[j]);
#pragma unroll
        for (int off = 16; off; off >>= 1)
            v += __shfl_xor_sync(0xffffffffu, v, off);
        if (lane == 0) wsum[wid] = v;
        __syncthreads();
        if (tid == 0) {
            float vs = wsum[0] + wsum[1];
            g_partial[b] = sc - (Mtot + __logf(vs));
            __threadfence();
        }
    }

    // ---------------- merged deterministic final reduction (last block) ----------------
    __syncthreads();
    if (tid == 0) {
        unsigned int old = atomicAdd(&g_ctr, 1);
        is_last = (old == (unsigned int)(gridDim.x - 1));
    }
    __syncthreads();
    if (is_last) {
        __threadfence();
        float s = 0.f;
#pragma unroll
        for (int i = 0; i < NB / 64; i++)
            s += g_partial[tid + i * 64];
#pragma unroll
        for (int off = 16; off; off >>= 1)
            s += __shfl_xor_sync(0xffffffffu, s, off);
        if (lane == 0) wsum[wid] = s;
        __syncthreads();
        if (tid == 0) {
            out[0] = wsum[0] + wsum[1];
            g_ctr = 0;
        }
    }
}

extern "C" void kernel_launch(void* const* d_in, const int* in_sizes, int n_in,
                              void* d_out, int out_size) {
    const float* em    = (const float*)d_in[0];
    const float* trans = (const float*)d_in[1];
    const float* st    = (const float*)d_in[2];
    const float* et    = (const float*)d_in[3];
    const int*   tags  = (const int*)d_in[4];
    const int*   mask  = (const int*)d_in[5];

    crf_kernel<<<NB, 64>>>(em, trans, st, et, tags, mask, (float*)d_out);
}

// round 6
// speedup vs baseline: 1.0751x; 1.0751x over previous
#include <cuda_runtime.h>
#include <cstdint>
#include <cstddef>

#define NS 512
#define NB 1024
#define NT 64
#define CHAINS_PER_BLOCK 4
#define TPB (CHAINS_PER_BLOCK * 32)      // 128
#define GRID_BLOCKS (NB / CHAINS_PER_BLOCK)  // 256
#define QSTRIDE 68                        // 32 u64 lower half, pad 2, 32 upper, pad 2

__device__ float g_partial[NB];
__device__ unsigned int g_ctr = 0;

typedef unsigned long long u64;

__device__ __forceinline__ u64 pack2(float lo, float hi) {
    u64 r; asm("mov.b64 %0, {%1, %2};" : "=l"(r) : "f"(lo), "f"(hi)); return r;
}
__device__ __forceinline__ void unpack2(u64 v, float& lo, float& hi) {
    asm("mov.b64 {%0, %1}, %2;" : "=f"(lo), "=f"(hi) : "l"(v));
}
__device__ __forceinline__ void fma2(u64& acc, u64 a, u64 b) {
    asm("fma.rn.f32x2 %0, %1, %2, %0;" : "+l"(acc) : "l"(a), "l"(b));
}
__device__ __forceinline__ u64 add2(u64 a, u64 b) {
    u64 r; asm("add.rn.f32x2 %0, %1, %2;" : "=l"(r) : "l"(a), "l"(b)); return r;
}
__device__ __forceinline__ u64 mul2(u64 a, u64 b) {
    u64 r; asm("mul.rn.f32x2 %0, %1, %2;" : "=l"(r) : "l"(a), "l"(b)); return r;
}
__device__ __forceinline__ float frcp(float x) {
    float r; asm("rcp.approx.f32 %0, %1;" : "=f"(r) : "f"(x)); return r;
}
__device__ __forceinline__ void sts128(u64* p, float a, float b, float c, float d) {
    asm volatile("st.shared.v4.f32 [%0], {%1, %2, %3, %4};"
                 :: "l"(p), "f"(a), "f"(b), "f"(c), "f"(d) : "memory");
}

__global__ void __launch_bounds__(TPB, 2)
crf_kernel(const float* __restrict__ em,
           const float* __restrict__ trans,
           const float* __restrict__ start_t,
           const float* __restrict__ end_t,
           const int* __restrict__ tags,
           const int* __restrict__ mask,
           float* __restrict__ out) {
    // per-warp double-buffered duplicated-q: [warp][parity][QSTRIDE]
    __shared__ __align__(16) u64 qsm[CHAINS_PER_BLOCK][2][QSTRIDE];
    __shared__ float red_smem[4];
    __shared__ int is_last;

    const int tid  = threadIdx.x;
    const int wid  = tid >> 5;
    const int lane = tid & 31;
    const int b    = blockIdx.x * CHAINS_PER_BLOCK + wid;
    const int c    = lane & 15;      // column group: owns cols 4c..4c+3
    const int h    = lane >> 4;      // row half: rows 32h..32h+31
    const size_t SSTR = (size_t)NB * NT;

    // ---------------- numerator: gold-path score (lane-parallel over timesteps) ----------
    float sc = 0.f;
    {
        int msum = 0;
#pragma unroll
        for (int k = 0; k < 16; k++) {
            int s = 1 + lane + (k << 5);
            if (s < NS) {
                int tp = tags[(s - 1) * NB + b];
                int tc = tags[s * NB + b];
                int mv = mask[s * NB + b];
                float term = trans[tp * NT + tc] + em[((size_t)s * NB + b) * NT + tc];
                sc += term * (float)mv;
                msum += mv;
            }
        }
#pragma unroll
        for (int off = 16; off; off >>= 1) {
            sc   += __shfl_xor_sync(0xffffffffu, sc, off);
            msum += __shfl_xor_sync(0xffffffffu, msum, off);
        }
        int t0 = tags[b];
        sc += start_t[t0] + em[(size_t)b * NT + t0];
        int seq_end = mask[b] + msum - 1;
        int lt = tags[(size_t)seq_end * NB + b];
        sc += end_t[lt];
    }

    // ---------------- E = exp(trans): my 32 rows x my 4 cols, packed (64 u64) ----------
    u64 EA[32], EB[32];
#pragma unroll
    for (int i = 0; i < 32; i++) {
        float4 t4 = *reinterpret_cast<const float4*>(trans + (32 * h + i) * NT + 4 * c);
        EA[i] = pack2(__expf(t4.x), __expf(t4.y));
        EB[i] = pack2(__expf(t4.z), __expf(t4.w));
    }

    // ---------------- init recursion state ----------------
    const float* emj4 = em + (size_t)b * NT + 4 * c;   // float4 base for my cols
    const int sidx = 4 * c + ((c >= 8) ? 2 : 0);       // padded store index
    u64* const qpar0 = qsm[wid][0];
    u64* const qpar1 = qsm[wid][1];

    u64 y01 = 0, y23 = 0;          // h0 lanes: current y for cols 4c..4c+3 (packed)
    float4 pf0, pf1, pf2, pf3;     // em prefetch ring (h0 only)
    u64 eem01 = 0, eem23 = 0;      // exp(em) one step ahead (h0 only)
    if (h == 0) {
        float4 e0 = *reinterpret_cast<const float4*>(emj4);
        float4 s4 = *reinterpret_cast<const float4*>(start_t + 4 * c);
        y01 = pack2(__expf(s4.x + e0.x), __expf(s4.y + e0.y));
        y23 = pack2(__expf(s4.z + e0.z), __expf(s4.w + e0.w));
        float yy0, yy1, yy2, yy3;
        unpack2(y01, yy0, yy1); unpack2(y23, yy2, yy3);
        sts128(qpar1 + sidx,     yy0, yy0, yy1, yy1);
        sts128(qpar1 + sidx + 2, yy2, yy2, yy3, yy3);
        pf0 = *reinterpret_cast<const float4*>(emj4 + 1 * SSTR);
        pf1 = *reinterpret_cast<const float4*>(emj4 + 2 * SSTR);
        pf2 = *reinterpret_cast<const float4*>(emj4 + 3 * SSTR);
        pf3 = *reinterpret_cast<const float4*>(emj4 + 4 * SSTR);
        eem01 = pack2(__expf(pf0.x), __expf(pf0.y));
        eem23 = pack2(__expf(pf0.z), __expf(pf0.w));
    }
    float rcur = 1.0f, lpend = 0.f, Mtot = 0.f;        // uniform scalar chain
    int mkA = mask[1 * NB + b];
    int mkB = mask[2 * NB + b];
    __syncwarp();

#define CRF_STEP(S, PF_USE, PF_WR, MK_SLOT)                                          \
    do {                                                                             \
        if ((S) < NS) {                                                              \
            const int p = (S) & 1;                                                   \
            const int mk = MK_SLOT;                                                  \
            const u64* qh = qsm[wid][p] + h * 34;                                    \
            u64 A0 = 0, A1 = 0, A2 = 0, A3 = 0;                                      \
            _Pragma("unroll")                                                        \
            for (int i = 0; i < 32; i += 2) {                                        \
                ulonglong2 qq = *reinterpret_cast<const ulonglong2*>(qh + i);        \
                fma2(A0, qq.x, EA[i]);     fma2(A2, qq.x, EB[i]);                    \
                fma2(A1, qq.y, EA[i + 1]); fma2(A3, qq.y, EB[i + 1]);                \
            }                                                                        \
            u64 A01 = add2(A0, A1), A23 = add2(A2, A3);                              \
            A01 = add2(A01, __shfl_xor_sync(0xffffffffu, A01, 16));                  \
            A23 = add2(A23, __shfl_xor_sync(0xffffffffu, A23, 16));                  \
            float alo, ahi; unpack2(A01, alo, ahi);                                  \
            float a0raw = __shfl_sync(0xffffffffu, alo, 0);                          \
            if (h == 0) {                                                            \
                u64 rp = pack2(rcur, rcur);                                          \
                u64 c01 = mul2(mul2(A01, rp), eem01);                                \
                u64 c23 = mul2(mul2(A23, rp), eem23);                                \
                if (mk) { y01 = c01; y23 = c23; }                                    \
                float yy0, yy1, yy2, yy3;                                            \
                unpack2(y01, yy0, yy1); unpack2(y23, yy2, yy3);                      \
                u64* qn = qsm[wid][p ^ 1];                                           \
                sts128(qn + sidx,     yy0, yy0, yy1, yy1);                           \
                sts128(qn + sidx + 2, yy2, yy2, yy3, yy3);                           \
            }                                                                        \
            float u0n = a0raw * rcur;                                                \
            if (mk) { Mtot += lpend; lpend = __logf(u0n); rcur = frcp(u0n); }        \
            __syncwarp();                                                            \
            if (h == 0) {                                                            \
                eem01 = pack2(__expf(PF_USE.x), __expf(PF_USE.y));                   \
                eem23 = pack2(__expf(PF_USE.z), __expf(PF_USE.w));                   \
                if ((S) + 4 < NS)                                                    \
                    PF_WR = *reinterpret_cast<const float4*>(emj4 + (size_t)((S) + 4) * SSTR); \
            }                                                                        \
            if ((S) + 2 < NS)                                                        \
                MK_SLOT = mask[((S) + 2) * NB + b];                                  \
        }                                                                            \
    } while (0)

    for (int k = 0; k < 128; k++) {
        int sb = 1 + (k << 2);
        CRF_STEP(sb,     pf1, pf0, mkA);
        CRF_STEP(sb + 1, pf2, pf1, mkB);
        CRF_STEP(sb + 2, pf3, pf2, mkA);
        CRF_STEP(sb + 3, pf0, pf3, mkB);
    }
#undef CRF_STEP

    // ---------------- final: normalizer = Mtot + log( sum_j y_j * exp(end_j) ) ----------
    {
        float v = 0.f;
        if (h == 0) {
            float4 e4 = *reinterpret_cast<const float4*>(end_t + 4 * c);
            float yy0, yy1, yy2, yy3;
            unpack2(y01, yy0, yy1); unpack2(y23, yy2, yy3);
            v = yy0 * __expf(e4.x) + yy1 * __expf(e4.y)
              + yy2 * __expf(e4.z) + yy3 * __expf(e4.w);
        }
#pragma unroll
        for (int off = 16; off; off >>= 1)
            v += __shfl_xor_sync(0xffffffffu, v, off);
        if (lane == 0) {
            g_partial[b] = sc - (Mtot + __logf(v));
            __threadfence();
        }
    }

    // ---------------- merged deterministic final reduction (last block) ----------------
    __syncthreads();
    if (tid == 0) {
        unsigned int old = atomicAdd(&g_ctr, 1);
        is_last = (old == (unsigned int)(gridDim.x - 1));
    }
    __syncthreads();
    if (is_last) {
        __threadfence();
        float s = 0.f;
#pragma unroll
        for (int i = 0; i < NB / TPB; i++)
            s += g_partial[tid + i * TPB];
#pragma unroll
        for (int off = 16; off; off >>= 1)
            s += __shfl_xor_sync(0xffffffffu, s, off);
        if ((tid & 31) == 0) red_smem[tid >> 5] = s;
        __syncthreads();
        if (tid == 0) {
            out[0] = red_smem[0] + red_smem[1] + red_smem[2] + red_smem[3];
            g_ctr = 0;
        }
    }
}

extern "C" void kernel_launch(void* const* d_in, const int* in_sizes, int n_in,
                              void* d_out, int out_size) {
    const float* em    = (const float*)d_in[0];
    const float* trans = (const float*)d_in[1];
    const float* st    = (const float*)d_in[2];
    const float* et    = (const float*)d_in[3];
    const int*   tags  = (const int*)d_in[4];
    const int*   mask  = (const int*)d_in[5];

    crf_kernel<<<GRID_BLOCKS, TPB>>>(em, trans, st, et, tags, mask, (float*)d_out);
}

// round 7
// speedup vs baseline: 1.2255x; 1.1399x over previous
#include <cuda_runtime.h>
#include <cstdint>
#include <cstddef>

#define NS 512
#define NB 1024
#define NT 64
#define QSTRIDE 68   // 32 u64 (rows 0-31 region) + 2 pad + 32 u64 (rows 32-63) + 2 pad

__device__ float g_partial[NB];
__device__ unsigned int g_ctr = 0;

typedef unsigned long long u64;

__device__ __forceinline__ u64 pack2(float lo, float hi) {
    u64 r; asm("mov.b64 %0, {%1, %2};" : "=l"(r) : "f"(lo), "f"(hi)); return r;
}
__device__ __forceinline__ void unpack2(u64 v, float& lo, float& hi) {
    asm("mov.b64 {%0, %1}, %2;" : "=f"(lo), "=f"(hi) : "l"(v));
}
__device__ __forceinline__ void fma2(u64& acc, u64 a, u64 b) {
    asm("fma.rn.f32x2 %0, %1, %2, %0;" : "+l"(acc) : "l"(a), "l"(b));
}
__device__ __forceinline__ u64 add2(u64 a, u64 b) {
    u64 r; asm("add.rn.f32x2 %0, %1, %2;" : "=l"(r) : "l"(a), "l"(b)); return r;
}
__device__ __forceinline__ u64 mul2(u64 a, u64 b) {
    u64 r; asm("mul.rn.f32x2 %0, %1, %2;" : "=l"(r) : "l"(a), "l"(b)); return r;
}
__device__ __forceinline__ float frcp(float x) {
    float r; asm("rcp.approx.f32 %0, %1;" : "=f"(r) : "f"(x)); return r;
}
__device__ __forceinline__ u64 shflx16_u64(u64 v) {
    unsigned lo = (unsigned)v, hi = (unsigned)(v >> 32);
    lo = __shfl_xor_sync(0xffffffffu, lo, 16);
    hi = __shfl_xor_sync(0xffffffffu, hi, 16);
    return ((u64)hi << 32) | lo;
}
__device__ __forceinline__ void sts128(u64* p, float a, float b, float c, float d) {
    asm volatile("st.shared.v4.f32 [%0], {%1, %2, %3, %4};"
                 :: "l"(p), "f"(a), "f"(b), "f"(c), "f"(d) : "memory");
}

__global__ void __launch_bounds__(32)
crf_kernel(const float* __restrict__ em,
           const float* __restrict__ trans,
           const float* __restrict__ start_t,
           const float* __restrict__ end_t,
           const int* __restrict__ tags,
           const int* __restrict__ mask,
           float* __restrict__ out) {
    __shared__ __align__(16) u64 qsm[2][QSTRIDE];

    const int lane = threadIdx.x;        // 0..31, one warp = one chain
    const int b    = blockIdx.x;
    const int c    = lane & 15;          // owns cols 4c..4c+3
    const int h    = lane >> 4;          // row half
    const size_t SSTR = (size_t)NB * NT;

    // ---------------- numerator: gold-path score ----------------
    float sc = 0.f;
    {
        int msum = 0;
#pragma unroll
        for (int k = 0; k < 16; k++) {
            int s = 1 + lane + (k << 5);
            if (s < NS) {
                int tp = tags[(s - 1) * NB + b];
                int tc = tags[s * NB + b];
                int mv = mask[s * NB + b];
                float term = trans[tp * NT + tc] + em[((size_t)s * NB + b) * NT + tc];
                sc += term * (float)mv;
                msum += mv;
            }
        }
#pragma unroll
        for (int off = 16; off; off >>= 1) {
            sc   += __shfl_xor_sync(0xffffffffu, sc, off);
            msum += __shfl_xor_sync(0xffffffffu, msum, off);
        }
        int t0 = tags[b];
        sc += start_t[t0] + em[(size_t)b * NT + t0];
        int seq_end = mask[b] + msum - 1;
        int lt = tags[(size_t)seq_end * NB + b];
        sc += end_t[lt];
    }

    // ---------------- E = exp(trans): my 32 rows x my 4 cols ----------------
    u64 EA[32], EB[32];
#pragma unroll
    for (int i = 0; i < 32; i++) {
        float4 t4 = *reinterpret_cast<const float4*>(trans + (32 * h + i) * NT + 4 * c);
        EA[i] = pack2(__expf(t4.x), __expf(t4.y));
        EB[i] = pack2(__expf(t4.z), __expf(t4.w));
    }

    // ---------------- init recursion state (all lanes symmetric) ----------------
    const float* emj4 = em + (size_t)b * NT + 4 * c;
    const int sidx = 4 * c + ((c >= 8) ? 2 : 0);   // padded store index

    u64 y01, y23;
    {
        float4 e0 = *reinterpret_cast<const float4*>(emj4);
        float4 s4 = *reinterpret_cast<const float4*>(start_t + 4 * c);
        y01 = pack2(__expf(s4.x + e0.x), __expf(s4.y + e0.y));
        y23 = pack2(__expf(s4.z + e0.z), __expf(s4.w + e0.w));
        float yy0, yy1, yy2, yy3;
        unpack2(y01, yy0, yy1); unpack2(y23, yy2, yy3);
        if (h == 0) {
            sts128(qsm[1] + sidx,     yy0, yy0, yy1, yy1);
            sts128(qsm[1] + sidx + 2, yy2, yy2, yy3, yy3);
        }
    }
    float4 pf0 = *reinterpret_cast<const float4*>(emj4 + 1 * SSTR);
    float4 pf1 = *reinterpret_cast<const float4*>(emj4 + 2 * SSTR);
    float4 pf2 = *reinterpret_cast<const float4*>(emj4 + 3 * SSTR);
    float4 pf3 = *reinterpret_cast<const float4*>(emj4 + 4 * SSTR);
    u64 eem01 = pack2(__expf(pf0.x), __expf(pf0.y));
    u64 eem23 = pack2(__expf(pf0.z), __expf(pf0.w));
    float rcur = 1.0f, lpend = 0.f, Mtot = 0.f;    // replicated in every lane
    int mkA = mask[1 * NB + b];
    int mkB = mask[2 * NB + b];
    __syncwarp();

#define CRF_STEP(S, PF_USE, PF_WR, MK_SLOT)                                          \
    do {                                                                             \
        if ((S) < NS) {                                                              \
            const int p = (S) & 1;                                                   \
            const int mk = MK_SLOT;                                                  \
            const u64* qh = qsm[p] + h * 34;                                         \
            u64 A0 = 0, A1 = 0, A2 = 0, A3 = 0;                                      \
            u64 B0 = 0, B1 = 0, B2 = 0, B3 = 0;                                      \
            _Pragma("unroll")                                                        \
            for (int i = 0; i < 32; i += 4) {                                        \
                ulonglong2 qq  = *reinterpret_cast<const ulonglong2*>(qh + i);       \
                ulonglong2 qq2 = *reinterpret_cast<const ulonglong2*>(qh + i + 2);   \
                fma2(A0, qq.x,  EA[i]);     fma2(B0, qq.x,  EB[i]);                  \
                fma2(A1, qq.y,  EA[i + 1]); fma2(B1, qq.y,  EB[i + 1]);              \
                fma2(A2, qq2.x, EA[i + 2]); fma2(B2, qq2.x, EB[i + 2]);              \
                fma2(A3, qq2.y, EA[i + 3]); fma2(B3, qq2.y, EB[i + 3]);              \
            }                                                                        \
            u64 A01 = add2(add2(A0, A1), add2(A2, A3));                              \
            u64 A23 = add2(add2(B0, B1), add2(B2, B3));                              \
            A01 = add2(A01, shflx16_u64(A01));                                       \
            A23 = add2(A23, shflx16_u64(A23));                                       \
            float alo, ahi; unpack2(A01, alo, ahi);                                  \
            float a0raw = __shfl_sync(0xffffffffu, alo, 0);                          \
            u64 rp = pack2(rcur, rcur);                                              \
            u64 c01 = mul2(mul2(A01, rp), eem01);                                    \
            u64 c23 = mul2(mul2(A23, rp), eem23);                                    \
            if (mk) { y01 = c01; y23 = c23; }                                        \
            float yy0, yy1, yy2, yy3;                                                \
            unpack2(y01, yy0, yy1); unpack2(y23, yy2, yy3);                          \
            u64* qn = qsm[p ^ 1];                                                    \
            if (h == 0) {                                                            \
                sts128(qn + sidx,     yy0, yy0, yy1, yy1);                           \
                sts128(qn + sidx + 2, yy2, yy2, yy3, yy3);                           \
            }                                                                        \
            float u0n = a0raw * rcur;                                                \
            if (mk) { Mtot += lpend; lpend = __logf(u0n); rcur = frcp(u0n); }        \
            __syncwarp();                                                            \
            eem01 = pack2(__expf(PF_USE.x), __expf(PF_USE.y));                       \
            eem23 = pack2(__expf(PF_USE.z), __expf(PF_USE.w));                       \
            if ((S) + 4 < NS)                                                        \
                PF_WR = *reinterpret_cast<const float4*>(emj4 + (size_t)((S) + 4) * SSTR); \
            if ((S) + 2 < NS)                                                        \
                MK_SLOT = mask[((S) + 2) * NB + b];                                  \
        }                                                                            \
    } while (0)

    for (int k = 0; k < 128; k++) {
        int sb = 1 + (k << 2);
        CRF_STEP(sb,     pf1, pf0, mkA);
        CRF_STEP(sb + 1, pf2, pf1, mkB);
        CRF_STEP(sb + 2, pf3, pf2, mkA);
        CRF_STEP(sb + 3, pf0, pf3, mkB);
    }
#undef CRF_STEP

    // ---------------- normalizer = Mtot + lag-pending + log(sum_j y_j e^{end_j}) ------
    {
        float4 e4 = *reinterpret_cast<const float4*>(end_t + 4 * c);
        float yy0, yy1, yy2, yy3;
        unpack2(y01, yy0, yy1); unpack2(y23, yy2, yy3);
        float v = yy0 * __expf(e4.x) + yy1 * __expf(e4.y)
                + yy2 * __expf(e4.z) + yy3 * __expf(e4.w);
#pragma unroll
        for (int off = 16; off; off >>= 1)
            v += __shfl_xor_sync(0xffffffffu, v, off);
        v *= 0.5f;   // both halves contributed identical copies
        if (lane == 0) {
            g_partial[b] = sc - (Mtot + __logf(v));
            __threadfence();
        }
    }

    // ---------------- merged deterministic final reduction (last block) ----------------
    __syncwarp();
    int last = 0;
    if (lane == 0) {
        unsigned int old = atomicAdd(&g_ctr, 1);
        last = (old == (unsigned int)(gridDim.x - 1));
    }
    last = __shfl_sync(0xffffffffu, last, 0);
    if (last) {
        __threadfence();
        float s = 0.f;
#pragma unroll
        for (int i = 0; i < NB / 32; i++)
            s += g_partial[lane + i * 32];
#pragma unroll
        for (int off = 16; off; off >>= 1)
            s += __shfl_xor_sync(0xffffffffu, s, off);
        if (lane == 0) { out[0] = s; g_ctr = 0; }
    }
}

extern "C" void kernel_launch(void* const* d_in, const int* in_sizes, int n_in,
                              void* d_out, int out_size) {
    const float* em    = (const float*)d_in[0];
    const float* trans = (const float*)d_in[1];
    const float* st    = (const float*)d_in[2];
    const float* et    = (const float*)d_in[3];
    const int*   tags  = (const int*)d_in[4];
    const int*   mask  = (const int*)d_in[5];

    crf_kernel<<<NB, 32>>>(em, trans, st, et, tags, mask, (float*)d_out);
}